// round 13
// baseline (speedup 1.0000x reference)
#include <cuda_runtime.h>
#include <cstdint>
#include <cstddef>

// 2-layer LSTM: B=32, T=512, IN=2048, H=512, fp32.
// gemm0 -> [reset] rec0 -> gemm1 -> [reset] rec1 (graph-capturable).
// Recurrence: 2 independent batch-groups x 64 blocks; block owns 8 units.

typedef unsigned long long ull;

#define Bb 32
#define Tt 512
#define Hh 512
#define Gg 2048          // 4*H
#define Mm 16384         // B*T
#define BPG 64u          // blocks per group
#define NGRP 2

// ---- device scratch (no allocations allowed) -------------------------------
__device__ float g_xgt[(size_t)Tt * Gg * Bb];   // [t][g][b]  128 MB (reused)
__device__ float g_h1[(size_t)Mm * Hh];         // layer-0 output [b*T+t][u]
__device__ ull   g_h2g[2 * NGRP * 256 * 16];    // h pairs: [par][grp][k2][b16]
__device__ unsigned g_barG[NGRP * 32];          // per-group counter (padded)
__device__ volatile unsigned g_relG[NGRP * 32]; // per-group release (padded)

// ---- packed f32x2 helpers --------------------------------------------------
__device__ __forceinline__ ull pk(float x, float y) {
    ull r; asm("mov.b64 %0,{%1,%2};" : "=l"(r) : "f"(x), "f"(y)); return r;
}
__device__ __forceinline__ void upk(ull v, float& x, float& y) {
    asm("mov.b64 {%0,%1},%2;" : "=f"(x), "=f"(y) : "l"(v));
}
__device__ __forceinline__ void fma2(ull& d, ull a, ull b) {
    asm("fma.rn.f32x2 %0,%1,%2,%0;" : "+l"(d) : "l"(a), "l"(b));
}
__device__ __forceinline__ float sigf(float x) { return 1.f / (1.f + __expf(-x)); }
__device__ __forceinline__ float tanh_f(float x) {
    float a = fabsf(x);
    float e = __expf(-2.f * a);
    float t = (1.f - e) / (1.f + e);
    return copysignf(t, x);
}

__global__ void reset_bar() {
    if (threadIdx.x < NGRP * 32) { g_barG[threadIdx.x] = 0u; g_relG[threadIdx.x] = 0u; }
}

// ============================================================================
// GEMM: g_xgt[t][g][b] = A[m][k] @ W[g][k]^T + (b1[g]+b2[g]),  m = b*T+t
// (unchanged — ~155 TF/s)
// ============================================================================
#define BM 128
#define BN 64
#define BK 16

__global__ __launch_bounds__(256) void gemm_bias(
    const float* __restrict__ A, const float* __restrict__ W,
    const float* __restrict__ b1, const float* __restrict__ b2, int K)
{
    __shared__ float As[BK][BM + 4];
    __shared__ float Bs[BK][BN + 4];
    const int tid = threadIdx.x;
    const int m0 = blockIdx.x * BM;
    const int n0 = blockIdx.y * BN;
    const int tx = tid & 15;
    const int ty = tid >> 4;

    ull acc[8][2];
    #pragma unroll
    for (int i = 0; i < 8; i++) { acc[i][0] = 0ull; acc[i][1] = 0ull; }

    for (int kt = 0; kt < K; kt += BK) {
        #pragma unroll
        for (int r = 0; r < 2; r++) {
            int f = tid + r * 256;
            int m = f >> 2, k4 = (f & 3) * 4;
            float4 v = *(const float4*)(A + (size_t)(m0 + m) * K + kt + k4);
            As[k4 + 0][m] = v.x; As[k4 + 1][m] = v.y;
            As[k4 + 2][m] = v.z; As[k4 + 3][m] = v.w;
        }
        {
            int n = tid >> 2, k4 = (tid & 3) * 4;
            float4 v = *(const float4*)(W + (size_t)(n0 + n) * K + kt + k4);
            Bs[k4 + 0][n] = v.x; Bs[k4 + 1][n] = v.y;
            Bs[k4 + 2][n] = v.z; Bs[k4 + 3][n] = v.w;
        }
        __syncthreads();
        #pragma unroll
        for (int kk = 0; kk < BK; kk++) {
            float4 a0 = *(const float4*)&As[kk][ty * 8];
            float4 a1 = *(const float4*)&As[kk][ty * 8 + 4];
            ulonglong2 bv = *(const ulonglong2*)&Bs[kk][tx * 4];
            float av[8] = {a0.x, a0.y, a0.z, a0.w, a1.x, a1.y, a1.z, a1.w};
            #pragma unroll
            for (int i = 0; i < 8; i++) {
                ull d = pk(av[i], av[i]);
                fma2(acc[i][0], d, bv.x);
                fma2(acc[i][1], d, bv.y);
            }
        }
        __syncthreads();
    }

    float bias[4];
    #pragma unroll
    for (int c = 0; c < 4; c++) { int g = n0 + tx * 4 + c; bias[c] = b1[g] + b2[g]; }
    #pragma unroll
    for (int i = 0; i < 8; i++) {
        int m = m0 + ty * 8 + i;
        int b = m >> 9, t = m & 511;
        #pragma unroll
        for (int j = 0; j < 2; j++) {
            float v0, v1; upk(acc[i][j], v0, v1);
            int g = n0 + tx * 4 + j * 2;
            g_xgt[((size_t)t * Gg + g) * Bb + b]     = v0 + bias[j * 2];
            g_xgt[((size_t)t * Gg + g + 1) * Bb + b] = v1 + bias[j * 2 + 1];
        }
    }
}

// ============================================================================
// Recurrence. Grid 128 = 2 groups x 64 blocks. Group grp owns batches
// 16*grp..+15; block owns units u0=(bid&63)*8 (32 gate-rows).
// smem: w_s [256 k2][32 r] ull (natural k-pairs, row-interleaved),
//       h_s [256 k2][16 b] ull (identical layout to g_h2g slice -> memcpy),
//       part [8 kc][32 r][17 pad] float.
// Warp w: k2 chunk [w*32,(w+1)*32). Lane: rg=lane&3 (rows jj*8+rg*2{,+1},
// jj=0..3), bp=lane>>2 (batches 2bp,2bp+1). 5 LDS.128 (1 phase each) / 16 fma2.
// Accum pair = (even-k sum, odd-k sum); horizontal add at partial store.
// ============================================================================
#define SM_W   (256 * 32 * 8)           // 65536
#define SM_H   (256 * 16 * 8)           // 32768
#define SM_P   (8 * 32 * 17 * 4)        // 17408
#define SMEM_REC (SM_W + SM_H + SM_P)

__global__ __launch_bounds__(256) void lstm_rec(
    const float* __restrict__ Whh, float* __restrict__ hseq)
{
    extern __shared__ char smraw[];
    ull* w_s = (ull*)smraw;                      // [k2][r]
    ull* h_s = (ull*)(smraw + SM_W);             // [k2][b]
    float* part = (float*)(smraw + SM_W + SM_H); // [(kc*32+r)*17 + b]

    const int tid  = threadIdx.x;
    const int w    = tid >> 5;
    const int lane = tid & 31;
    const int bid  = blockIdx.x;
    const int grp  = bid >> 6;                   // 0 or 1
    const int blk  = bid & 63;
    const int u0   = blk * 8;
    const int bg0  = grp * 16;

    const int rg = lane & 3;                     // row-pair selector
    const int bp = lane >> 2;                    // batches 2bp, 2bp+1
    const int k0 = w * 32;                       // k2 chunk

    // ---- init: W_hh rows -> w_s[k2][r] as natural k-pairs ----
    // row r (0..31): gate=r>>3, unit=u0+(r&7); global row gr = gate*512+unit.
    for (int i = tid; i < 32 * 256; i += 256) {
        int r = i & 31, k2 = i >> 5;
        int gr = (r >> 3) * Hh + u0 + (r & 7);
        w_s[(size_t)k2 * 32 + r] = *(const ull*)(Whh + (size_t)gr * Hh + 2 * k2);
    }
    // zero own h entries (parity 0): k2 = u0/2 + 0..3, all 16 b
    if (tid < 64) {
        int k2 = (u0 >> 1) + (tid >> 4), b = tid & 15;
        g_h2g[(size_t)(0 * NGRP + grp) * 4096 + k2 * 16 + b] = 0ull;
    }

    // pointwise ownership: tid<128: unit pu = tid&7, batch pbl = tid>>3
    const int pu  = tid & 7;
    const int pbl = tid >> 3;
    float c = 0.f;

    __syncthreads();
    unsigned bi = 1;
    if (tid == 0) {                              // barrier 0: zeros visible
        __threadfence();
        unsigned old = atomicAdd(&g_barG[grp * 32], 1u);
        if (old == BPG * bi - 1u) g_relG[grp * 32] = bi;
        while (g_relG[grp * 32] < bi) {}
        __threadfence();
    }
    __syncthreads();
    bi++;

    for (int t = 0; t < Tt; t++) {
        // ---- xg for pointwise (tid<128: 4 gates) ----
        float xv0 = 0.f, xv1 = 0.f, xv2 = 0.f, xv3 = 0.f;
        if (tid < 128) {
            const float* xb = g_xgt + ((size_t)t * Gg + u0 + pu) * Bb + bg0 + pbl;
            xv0 = __ldg(xb);
            xv1 = __ldg(xb + (size_t)Hh * Bb);
            xv2 = __ldg(xb + (size_t)2 * Hh * Bb);
            xv3 = __ldg(xb + (size_t)3 * Hh * Bb);
        }

        // ---- stage h (32KB, layout-identical memcpy) ----
        {
            const ulonglong2* src = (const ulonglong2*)(g_h2g +
                (size_t)((t & 1) * NGRP + grp) * 4096);
            ulonglong2* dst = (ulonglong2*)h_s;
            #pragma unroll
            for (int j = 0; j < 8; j++)
                dst[tid + j * 256] = __ldcg(src + tid + j * 256);
        }
        __syncthreads();

        // ---- partials: 8 rows x 2 batches x 64 k per lane ----
        ull acc[4][2][2];
        #pragma unroll
        for (int a = 0; a < 4; a++)
            #pragma unroll
            for (int s = 0; s < 2; s++) { acc[a][s][0] = 0ull; acc[a][s][1] = 0ull; }

        #pragma unroll 4
        for (int k2i = 0; k2i < 32; k2i++) {
            int k2 = k0 + k2i;
            ulonglong2 hv = *(const ulonglong2*)(h_s + (size_t)k2 * 16 + bp * 2);
            const ull* wr = w_s + (size_t)k2 * 32 + rg * 2;
            ulonglong2 w0 = *(const ulonglong2*)(wr);       // rows rg*2, rg*2+1
            ulonglong2 w1 = *(const ulonglong2*)(wr + 8);   // rows 8+rg*2, +1
            ulonglong2 w2 = *(const ulonglong2*)(wr + 16);  // rows 16+rg*2, +1
            ulonglong2 w3 = *(const ulonglong2*)(wr + 24);  // rows 24+rg*2, +1
            fma2(acc[0][0][0], w0.x, hv.x); fma2(acc[0][0][1], w0.x, hv.y);
            fma2(acc[0][1][0], w0.y, hv.x); fma2(acc[0][1][1], w0.y, hv.y);
            fma2(acc[1][0][0], w1.x, hv.x); fma2(acc[1][0][1], w1.x, hv.y);
            fma2(acc[1][1][0], w1.y, hv.x); fma2(acc[1][1][1], w1.y, hv.y);
            fma2(acc[2][0][0], w2.x, hv.x); fma2(acc[2][0][1], w2.x, hv.y);
            fma2(acc[2][1][0], w2.y, hv.x); fma2(acc[2][1][1], w2.y, hv.y);
            fma2(acc[3][0][0], w3.x, hv.x); fma2(acc[3][0][1], w3.x, hv.y);
            fma2(acc[3][1][0], w3.y, hv.x); fma2(acc[3][1][1], w3.y, hv.y);
        }
        // horizontal add (even-k + odd-k) and store partials
        #pragma unroll
        for (int jj = 0; jj < 4; jj++)
            #pragma unroll
            for (int s = 0; s < 2; s++) {
                int r = jj * 8 + rg * 2 + s;
                float x0, y0, x1, y1;
                upk(acc[jj][s][0], x0, y0);
                upk(acc[jj][s][1], x1, y1);
                part[((size_t)w * 32 + r) * 17 + bp * 2]     = x0 + y0;
                part[((size_t)w * 32 + r) * 17 + bp * 2 + 1] = x1 + y1;
            }
        __syncthreads();

        // ---- reduce + activations + cell update (tid<128) ----
        if (tid < 128) {
            float pre[4] = {xv0, xv1, xv2, xv3};
            #pragma unroll
            for (int g = 0; g < 4; g++) {
                int r = g * 8 + pu;
                #pragma unroll
                for (int kc = 0; kc < 8; kc++)
                    pre[g] += part[((size_t)kc * 32 + r) * 17 + pbl];
            }
            float iv = sigf(pre[0]);
            float fv = sigf(pre[1]);
            float gv = tanh_f(pre[2]);
            float ov = sigf(pre[3]);
            c = fv * c + iv * gv;
            float h = ov * tanh_f(c);
            hseq[((size_t)(bg0 + pbl) * Tt + t) * Hh + u0 + pu] = h;   // [B][T][H]
            float h_hi = __shfl_down_sync(0xFFFFFFFFu, h, 1);          // unit pair
            if ((pu & 1) == 0)
                g_h2g[(size_t)(((t + 1) & 1) * NGRP + grp) * 4096 +
                      ((u0 + pu) >> 1) * 16 + pbl] = pk(h, h_hi);
        }
        __threadfence();
        __syncthreads();

        // ---- per-group grid barrier (proven protocol, width 64) ----
        if (tid == 0) {
            unsigned old = atomicAdd(&g_barG[grp * 32], 1u);
            if (old == BPG * bi - 1u) g_relG[grp * 32] = bi;
            while (g_relG[grp * 32] < bi) {}
            __threadfence();
        }
        __syncthreads();
        bi++;
    }
}

// ============================================================================
extern "C" void kernel_launch(void* const* d_in, const int* in_sizes, int n_in,
                              void* d_out, int out_size)
{
    const float* feats = (const float*)d_in[0];
    const float* Wih0  = (const float*)d_in[1];
    const float* Whh0  = (const float*)d_in[2];
    const float* bih0  = (const float*)d_in[3];
    const float* bhh0  = (const float*)d_in[4];
    const float* Wih1  = (const float*)d_in[5];
    const float* Whh1  = (const float*)d_in[6];
    const float* bih1  = (const float*)d_in[7];
    const float* bhh1  = (const float*)d_in[8];
    float* out = (float*)d_out;

    cudaFuncSetAttribute(lstm_rec, cudaFuncAttributeMaxDynamicSharedMemorySize, SMEM_REC);

    float* h1_ptr = nullptr;
    cudaGetSymbolAddress((void**)&h1_ptr, g_h1);

    dim3 ggrid(Mm / BM, Gg / BN);  // (128, 32)

    gemm_bias<<<ggrid, 256>>>(feats, Wih0, bih0, bhh0, 2048);
    reset_bar<<<1, 64>>>();
    lstm_rec<<<128, 256, SMEM_REC>>>(Whh0, h1_ptr);

    gemm_bias<<<ggrid, 256>>>(h1_ptr, Wih1, bih1, bhh1, 512);
    reset_bar<<<1, 64>>>();
    lstm_rec<<<128, 256, SMEM_REC>>>(Whh1, out);
}

// round 15
// speedup vs baseline: 1.4456x; 1.4456x over previous
#include <cuda_runtime.h>
#include <cstdint>
#include <cstddef>

// 2-layer LSTM: B=32, T=512, IN=2048, H=512, fp32.
// gemm0 -> [reset] -> fused wavefront recurrence (both layers, 513 rounds).
// Blocks 0-63: layer 1 (8 units each). Blocks 64-127: layer 2, lagged 1 step
// (computes gates = bias + W_ih1@h1(t) + W_hh1@h2(t-1) inline; no gemm1).

typedef unsigned long long ull;

#define Bb 32
#define Tt 512
#define Hh 512
#define Gg 2048
#define Mm 16384
#define NBLK 128u
#define RND 513

// ---- device scratch --------------------------------------------------------
__device__ float g_xgt[(size_t)Tt * Gg * Bb];   // [t][g][b] from gemm0
__device__ ull   g_h1t[2][256 * 32];            // h1 unit-pairs [par][k2][b]
__device__ ull   g_h2t[2][256 * 32];            // h2 unit-pairs [par][k2][b]
__device__ unsigned g_bar;
__device__ volatile unsigned g_rel;

// ---- packed f32x2 helpers --------------------------------------------------
__device__ __forceinline__ ull pk(float x, float y) {
    ull r; asm("mov.b64 %0,{%1,%2};" : "=l"(r) : "f"(x), "f"(y)); return r;
}
__device__ __forceinline__ void upk(ull v, float& x, float& y) {
    asm("mov.b64 {%0,%1},%2;" : "=f"(x), "=f"(y) : "l"(v));
}
__device__ __forceinline__ void fma2(ull& d, ull a, ull b) {
    asm("fma.rn.f32x2 %0,%1,%2,%0;" : "+l"(d) : "l"(a), "l"(b));
}
__device__ __forceinline__ float sigf(float x) { return 1.f / (1.f + __expf(-x)); }
__device__ __forceinline__ float tanh_f(float x) {
    float a = fabsf(x);
    float e = __expf(-2.f * a);
    float t = (1.f - e) / (1.f + e);
    return copysignf(t, x);
}

__global__ void reset_bar() { g_bar = 0u; g_rel = 0u; }

// ============================================================================
// GEMM (unchanged, ~155 TF/s): g_xgt[t][g][b] = feats @ W_ih0^T + (b_ih0+b_hh0)
// ============================================================================
#define BM 128
#define BN 64
#define BK 16

__global__ __launch_bounds__(256) void gemm_bias(
    const float* __restrict__ A, const float* __restrict__ W,
    const float* __restrict__ b1, const float* __restrict__ b2, int K)
{
    __shared__ float As[BK][BM + 4];
    __shared__ float Bs[BK][BN + 4];
    const int tid = threadIdx.x;
    const int m0 = blockIdx.x * BM;
    const int n0 = blockIdx.y * BN;
    const int tx = tid & 15;
    const int ty = tid >> 4;

    ull acc[8][2];
    #pragma unroll
    for (int i = 0; i < 8; i++) { acc[i][0] = 0ull; acc[i][1] = 0ull; }

    for (int kt = 0; kt < K; kt += BK) {
        #pragma unroll
        for (int r = 0; r < 2; r++) {
            int f = tid + r * 256;
            int m = f >> 2, k4 = (f & 3) * 4;
            float4 v = *(const float4*)(A + (size_t)(m0 + m) * K + kt + k4);
            As[k4 + 0][m] = v.x; As[k4 + 1][m] = v.y;
            As[k4 + 2][m] = v.z; As[k4 + 3][m] = v.w;
        }
        {
            int n = tid >> 2, k4 = (tid & 3) * 4;
            float4 v = *(const float4*)(W + (size_t)(n0 + n) * K + kt + k4);
            Bs[k4 + 0][n] = v.x; Bs[k4 + 1][n] = v.y;
            Bs[k4 + 2][n] = v.z; Bs[k4 + 3][n] = v.w;
        }
        __syncthreads();
        #pragma unroll
        for (int kk = 0; kk < BK; kk++) {
            float4 a0 = *(const float4*)&As[kk][ty * 8];
            float4 a1 = *(const float4*)&As[kk][ty * 8 + 4];
            ulonglong2 bv = *(const ulonglong2*)&Bs[kk][tx * 4];
            float av[8] = {a0.x, a0.y, a0.z, a0.w, a1.x, a1.y, a1.z, a1.w};
            #pragma unroll
            for (int i = 0; i < 8; i++) {
                ull d = pk(av[i], av[i]);
                fma2(acc[i][0], d, bv.x);
                fma2(acc[i][1], d, bv.y);
            }
        }
        __syncthreads();
    }

    float bias[4];
    #pragma unroll
    for (int c = 0; c < 4; c++) { int g = n0 + tx * 4 + c; bias[c] = b1[g] + b2[g]; }
    #pragma unroll
    for (int i = 0; i < 8; i++) {
        int m = m0 + ty * 8 + i;
        int b = m >> 9, t = m & 511;
        #pragma unroll
        for (int j = 0; j < 2; j++) {
            float v0, v1; upk(acc[i][j], v0, v1);
            int g = n0 + tx * 4 + j * 2;
            g_xgt[((size_t)t * Gg + g) * Bb + b]     = v0 + bias[j * 2];
            g_xgt[((size_t)t * Gg + g + 1) * Bb + b] = v1 + bias[j * 2 + 1];
        }
    }
}

// ---- fused-recurrence helpers ----------------------------------------------
// stage 64KB h buffer (256 k2-rows x 32 b, ull) smem<-global, L2 path
__device__ __forceinline__ void stage64(ull* h_s, const ull* src, int tid) {
    const ulonglong2* s = (const ulonglong2*)src;
    ulonglong2* d = (ulonglong2*)h_s;
    #pragma unroll
    for (int j = 0; j < 16; j++)
        d[tid + j * 256] = __ldcg(s + tid + j * 256);
}

// accumulate one 64-k2 chunk: 4 rows x 4 batches per lane, natural k-pairs
__device__ __forceinline__ void accum_chunk(
    ull acc[4][4], const ull* __restrict__ wbase, const ull* __restrict__ h_s,
    int kc, int half, int rg, int bp)
{
    const ull* wp = wbase + (size_t)(kc * 64) * 32 + half * 16 + rg * 2;
    const ull* hp = h_s + (size_t)(kc * 64) * 32 + bp * 4;
    #pragma unroll 2
    for (int i = 0; i < 64; i++) {
        ulonglong2 wa = *(const ulonglong2*)(wp);       // rows rg*2, rg*2+1
        ulonglong2 wb = *(const ulonglong2*)(wp + 8);   // rows rg*2+8, rg*2+9
        ulonglong2 ha = *(const ulonglong2*)(hp);       // batches 4bp, 4bp+1
        ulonglong2 hb = *(const ulonglong2*)(hp + 2);   // batches 4bp+2, 4bp+3
        fma2(acc[0][0], wa.x, ha.x); fma2(acc[0][1], wa.x, ha.y);
        fma2(acc[0][2], wa.x, hb.x); fma2(acc[0][3], wa.x, hb.y);
        fma2(acc[1][0], wa.y, ha.x); fma2(acc[1][1], wa.y, ha.y);
        fma2(acc[1][2], wa.y, hb.x); fma2(acc[1][3], wa.y, hb.y);
        fma2(acc[2][0], wb.x, ha.x); fma2(acc[2][1], wb.x, ha.y);
        fma2(acc[2][2], wb.x, hb.x); fma2(acc[2][3], wb.x, hb.y);
        fma2(acc[3][0], wb.y, ha.x); fma2(acc[3][1], wb.y, ha.y);
        fma2(acc[3][2], wb.y, hb.x); fma2(acc[3][3], wb.y, hb.y);
        wp += 32; hp += 32;
    }
}

// ============================================================================
// Fused wavefront recurrence. smem: w_s [512 k2][32 r] ull (128KB; layer-1
// uses first 256 k2), h_s [256 k2][32 b] ull (64KB), part [4][32][36] f, bias.
// Warp w: half=w>>2 (rows half*16..+15), kc=w&3 (64-k2 chunk). Lane: rg=lane&3
// (rows rg*2,+1,+8,+9 in half), bp=lane>>2 (batches 4bp..4bp+3).
// Pointwise: du=tid&7, b=tid>>3 (all 256 threads).
// ============================================================================
#define SM_W    (512 * 32 * 8)           // 131072
#define SM_H    (256 * 32 * 8)           // 65536
#define SM_P    (4 * 32 * 36 * 4)        // 18432
#define SMEM_FUSED (SM_W + SM_H + SM_P + 128)

__global__ __launch_bounds__(256) void lstm_fused(
    const float* __restrict__ Whh0,
    const float* __restrict__ Wih1, const float* __restrict__ Whh1,
    const float* __restrict__ bih1, const float* __restrict__ bhh1,
    float* __restrict__ out)
{
    extern __shared__ char smraw[];
    ull* w_s = (ull*)smraw;
    ull* h_s = (ull*)(smraw + SM_W);
    float* part = (float*)(smraw + SM_W + SM_H);
    float* bias_s = (float*)(smraw + SM_W + SM_H + SM_P);

    const int tid  = threadIdx.x;
    const int w    = tid >> 5;
    const int lane = tid & 31;
    const int lay  = blockIdx.x >> 6;            // 0: layer1, 1: layer2
    const int u0   = (blockIdx.x & 63) * 8;

    const int half = w >> 2;
    const int kc   = w & 3;
    const int rg   = lane & 3;
    const int bp   = lane >> 2;
    const int du   = tid & 7;                    // pointwise unit
    const int b    = tid >> 3;                   // pointwise batch

    // ---- init W into smem as natural k-pairs: w_s[k2*32 + r] ----
    if (lay == 0) {
        for (int i = tid; i < 32 * 256; i += 256) {
            int r = i & 31, k2 = i >> 5;
            int gr = (r >> 3) * Hh + u0 + (r & 7);
            w_s[(size_t)k2 * 32 + r] = *(const ull*)(Whh0 + (size_t)gr * Hh + 2 * k2);
        }
    } else {
        for (int i = tid; i < 32 * 512; i += 256) {
            int r = i & 31, k2 = i >> 5;
            int gr = (r >> 3) * Hh + u0 + (r & 7);
            const float* src = (k2 < 256)
                ? (Wih1 + (size_t)gr * Hh + 2 * k2)
                : (Whh1 + (size_t)gr * Hh + 2 * (k2 - 256));
            w_s[(size_t)k2 * 32 + r] = *(const ull*)src;
        }
        if (tid < 32) {
            int gr = (tid >> 3) * Hh + u0 + (tid & 7);
            bias_s[tid] = bih1[gr] + bhh1[gr];
        }
    }
    // zero parity-1 state slices (h(-1) = 0)
    if (tid < 128) {
        int k2 = (u0 >> 1) + (tid >> 5), bb = tid & 31;
        if (lay == 0) g_h1t[1][k2 * 32 + bb] = 0ull;
        else          g_h2t[1][k2 * 32 + bb] = 0ull;
    }
    float c = 0.f;

    __syncthreads();
    unsigned bi = 1;
    if (tid == 0) {                              // barrier 0 (proven protocol)
        __threadfence();
        unsigned old = atomicAdd(&g_bar, 1u);
        if (old == NBLK * bi - 1u) g_rel = bi;
        while (g_rel < bi) {}
        __threadfence();
    }
    __syncthreads();
    bi++;

    for (int r = 0; r < RND; r++) {
        const bool active = (lay == 0) ? (r < Tt) : (r >= 1);
        if (active) {
            const int t = (lay == 0) ? r : r - 1;

            // layer-1: prefetch xg (gemm0 output) for pointwise
            float xv0 = 0.f, xv1 = 0.f, xv2 = 0.f, xv3 = 0.f;
            if (lay == 0) {
                const float* xb = g_xgt + ((size_t)t * Gg + u0 + du) * Bb + b;
                xv0 = __ldg(xb);
                xv1 = __ldg(xb + (size_t)Hh * Bb);
                xv2 = __ldg(xb + (size_t)2 * Hh * Bb);
                xv3 = __ldg(xb + (size_t)3 * Hh * Bb);
            }

            // phase A: both layers consume h1(r-1)  (parity (r-1)&1)
            stage64(h_s, g_h1t[(r - 1) & 1], tid);
            __syncthreads();

            ull acc[4][4];
            #pragma unroll
            for (int i = 0; i < 4; i++)
                #pragma unroll
                for (int j = 0; j < 4; j++) acc[i][j] = 0ull;

            accum_chunk(acc, w_s, h_s, kc, half, rg, bp);

            if (lay == 1) {
                __syncthreads();                     // all done reading h1
                stage64(h_s, g_h2t[r & 1], tid);     // h2(r-2), parity r&1
                __syncthreads();
                accum_chunk(acc, w_s + 256 * 32, h_s, kc, half, rg, bp);
            }

            // store partials (horizontal even+odd add)
            #pragma unroll
            for (int j = 0; j < 4; j++) {
                int rr = half * 16 + rg * 2 + (j & 1) + (j >> 1) * 8;
                #pragma unroll
                for (int cc = 0; cc < 4; cc++) {
                    float x, y; upk(acc[j][cc], x, y);
                    part[((size_t)kc * 32 + rr) * 36 + bp * 4 + cc] = x + y;
                }
            }
            __syncthreads();

            // reduce + activations + cell update (all 256 threads: du, b)
            {
                float pre[4];
                #pragma unroll
                for (int g = 0; g < 4; g++) {
                    float s0 = (lay == 0)
                        ? (g == 0 ? xv0 : g == 1 ? xv1 : g == 2 ? xv2 : xv3)
                        : bias_s[g * 8 + du];
                    #pragma unroll
                    for (int q = 0; q < 4; q++)
                        s0 += part[((size_t)q * 32 + g * 8 + du) * 36 + b];
                    pre[g] = s0;
                }
                float iv = sigf(pre[0]);
                float fv = sigf(pre[1]);
                float gv = tanh_f(pre[2]);
                float ov = sigf(pre[3]);
                c = fv * c + iv * gv;
                float h = ov * tanh_f(c);
                float h_hi = __shfl_down_sync(0xFFFFFFFFu, h, 1);  // unit pair
                if (lay == 0) {
                    if ((du & 1) == 0)
                        g_h1t[r & 1][((u0 + du) >> 1) * 32 + b] = pk(h, h_hi);
                } else {
                    out[((size_t)b * Tt + t) * Hh + u0 + du] = h;
                    if ((du & 1) == 0)
                        g_h2t[(r - 1) & 1][((u0 + du) >> 1) * 32 + b] = pk(h, h_hi);
                }
            }
        }
        __threadfence();
        __syncthreads();
        if (tid == 0) {                              // grid barrier (proven)
            unsigned old = atomicAdd(&g_bar, 1u);
            if (old == NBLK * bi - 1u) g_rel = bi;
            while (g_rel < bi) {}
            __threadfence();
        }
        __syncthreads();
        bi++;
    }
}

// ============================================================================
extern "C" void kernel_launch(void* const* d_in, const int* in_sizes, int n_in,
                              void* d_out, int out_size)
{
    const float* feats = (const float*)d_in[0];
    const float* Wih0  = (const float*)d_in[1];
    const float* Whh0  = (const float*)d_in[2];
    const float* bih0  = (const float*)d_in[3];
    const float* bhh0  = (const float*)d_in[4];
    const float* Wih1  = (const float*)d_in[5];
    const float* Whh1  = (const float*)d_in[6];
    const float* bih1  = (const float*)d_in[7];
    const float* bhh1  = (const float*)d_in[8];
    float* out = (float*)d_out;

    cudaFuncSetAttribute(lstm_fused, cudaFuncAttributeMaxDynamicSharedMemorySize,
                         SMEM_FUSED);

    dim3 ggrid(Mm / BM, Gg / BN);  // (128, 32)

    gemm_bias<<<ggrid, 256>>>(feats, Wih0, bih0, bhh0, 2048);
    reset_bar<<<1, 1>>>();
    lstm_fused<<<128, 256, SMEM_FUSED>>>(Whh0, Wih1, Whh1, bih1, bhh1, out);
}

// round 17
// speedup vs baseline: 1.4522x; 1.0046x over previous
#include <cuda_runtime.h>
#include <cstdint>
#include <cstddef>

// 2-layer LSTM: B=32, T=512, IN=2048, H=512, fp32.
// gemm0 -> [reset] rec0 -> gemm1 -> [reset] rec1 (graph-capturable).
// R16: R10 recurrence with 512 threads/block (4 warps/SMSP latency hiding).

typedef unsigned long long ull;

#define Bb 32
#define Tt 512
#define Hh 512
#define Gg 2048          // 4*H
#define Mm 16384         // B*T
#define NBLK 128u
#define NTH 512

// ---- device scratch (no allocations allowed) -------------------------------
__device__ float g_xgt[(size_t)Tt * Gg * Bb];   // [t][g][b]  128 MB (reused)
__device__ float g_h1[(size_t)Mm * Hh];         // layer-0 output [b*T+t][u]
__device__ float g_ht[2][Hh * Bb];              // hidden state, layout [u][b]
__device__ unsigned g_bar;
__device__ volatile unsigned g_rel;

// ---- packed f32x2 helpers --------------------------------------------------
__device__ __forceinline__ ull pk(float x, float y) {
    ull r; asm("mov.b64 %0,{%1,%2};" : "=l"(r) : "f"(x), "f"(y)); return r;
}
__device__ __forceinline__ void upk(ull v, float& x, float& y) {
    asm("mov.b64 {%0,%1},%2;" : "=f"(x), "=f"(y) : "l"(v));
}
__device__ __forceinline__ void fma2(ull& d, ull a, ull b) {
    asm("fma.rn.f32x2 %0,%1,%2,%0;" : "+l"(d) : "l"(a), "l"(b));
}
__device__ __forceinline__ ull add2(ull a, ull b) {
    ull r; asm("add.rn.f32x2 %0,%1,%2;" : "=l"(r) : "l"(a), "l"(b)); return r;
}
__device__ __forceinline__ float sigf(float x) { return 1.f / (1.f + __expf(-x)); }
__device__ __forceinline__ float tanh_f(float x) {
    float a = fabsf(x);
    float e = __expf(-2.f * a);
    float t = (1.f - e) / (1.f + e);
    return copysignf(t, x);
}

__global__ void reset_bar() { g_bar = 0u; g_rel = 0u; }

// ============================================================================
// GEMM: g_xgt[t][g][b] = A[m][k] @ W[g][k]^T + (b1[g]+b2[g]),  m = b*T+t
// (unchanged — ~155 TF/s ≈ f32x2 peak)
// ============================================================================
#define BM 128
#define BN 64
#define BK 16

__global__ __launch_bounds__(256) void gemm_bias(
    const float* __restrict__ A, const float* __restrict__ W,
    const float* __restrict__ b1, const float* __restrict__ b2, int K)
{
    __shared__ float As[BK][BM + 4];
    __shared__ float Bs[BK][BN + 4];
    const int tid = threadIdx.x;
    const int m0 = blockIdx.x * BM;
    const int n0 = blockIdx.y * BN;
    const int tx = tid & 15;
    const int ty = tid >> 4;

    ull acc[8][2];
    #pragma unroll
    for (int i = 0; i < 8; i++) { acc[i][0] = 0ull; acc[i][1] = 0ull; }

    for (int kt = 0; kt < K; kt += BK) {
        #pragma unroll
        for (int r = 0; r < 2; r++) {
            int f = tid + r * 256;
            int m = f >> 2, k4 = (f & 3) * 4;
            float4 v = *(const float4*)(A + (size_t)(m0 + m) * K + kt + k4);
            As[k4 + 0][m] = v.x; As[k4 + 1][m] = v.y;
            As[k4 + 2][m] = v.z; As[k4 + 3][m] = v.w;
        }
        {
            int n = tid >> 2, k4 = (tid & 3) * 4;
            float4 v = *(const float4*)(W + (size_t)(n0 + n) * K + kt + k4);
            Bs[k4 + 0][n] = v.x; Bs[k4 + 1][n] = v.y;
            Bs[k4 + 2][n] = v.z; Bs[k4 + 3][n] = v.w;
        }
        __syncthreads();
        #pragma unroll
        for (int kk = 0; kk < BK; kk++) {
            float4 a0 = *(const float4*)&As[kk][ty * 8];
            float4 a1 = *(const float4*)&As[kk][ty * 8 + 4];
            ulonglong2 bv = *(const ulonglong2*)&Bs[kk][tx * 4];
            float av[8] = {a0.x, a0.y, a0.z, a0.w, a1.x, a1.y, a1.z, a1.w};
            #pragma unroll
            for (int i = 0; i < 8; i++) {
                ull d = pk(av[i], av[i]);
                fma2(acc[i][0], d, bv.x);
                fma2(acc[i][1], d, bv.y);
            }
        }
        __syncthreads();
    }

    float bias[4];
    #pragma unroll
    for (int c = 0; c < 4; c++) { int g = n0 + tx * 4 + c; bias[c] = b1[g] + b2[g]; }
    #pragma unroll
    for (int i = 0; i < 8; i++) {
        int m = m0 + ty * 8 + i;
        int b = m >> 9, t = m & 511;
        #pragma unroll
        for (int j = 0; j < 2; j++) {
            float v0, v1; upk(acc[i][j], v0, v1);
            int g = n0 + tx * 4 + j * 2;
            g_xgt[((size_t)t * Gg + g) * Bb + b]     = v0 + bias[j * 2];
            g_xgt[((size_t)t * Gg + g + 1) * Bb + b] = v1 + bias[j * 2 + 1];
        }
    }
}

// ============================================================================
// Persistent recurrence: 128 blocks x 512 threads (16 warps, 4/SMSP).
// Identical structure/protocol to R10 (best passing). Warp w: k-chunk
// [w*32,(w+1)*32). Lane: p8=lane&7 -> batch-pairs p8,p8+8; rg=lane>>3 ->
// rows rg*4..rg*4+3. Partials [16 kc][16 r][16 p] ull; reduce q=0..15.
// ============================================================================
#define HS2 514
#define SM_H2   (16 * HS2 * 8)          // 65792
#define SM_W4   (16 * HS2 * 8)          // 65792
#define SM_PART (16 * 16 * 16 * 8)      // 32768
#define SMEM_REC (SM_H2 + SM_W4 + SM_PART)

__global__ __launch_bounds__(NTH) void lstm_rec(
    const float* __restrict__ Whh, float* __restrict__ hseq)
{
    extern __shared__ char smraw[];
    ull* h2 = (ull*)smraw;                       // [pair p][k]  (h[2p][k],h[2p+1][k])
    ull* w4 = (ull*)(smraw + SM_H2);             // [row r][k]   (w,w)
    ull* part = (ull*)(smraw + SM_H2 + SM_W4);   // [kc][r][p]
    float* partf = (float*)part;

    const int tid  = threadIdx.x;
    const int w    = tid >> 5;                   // 0..15
    const int lane = tid & 31;
    const int bid  = blockIdx.x;
    const int u0   = bid * 4;

    const int p8 = lane & 7;                     // batch-pairs p8, p8+8
    const int rg = lane >> 3;                    // rows rg*4 .. rg*4+3
    const int k0 = w * 32;                       // 32-float k-chunk per warp

    // ---- init: pack W_hh rows (duplicated pairs) into smem ----
    for (int i = tid; i < 16 * Hh; i += NTH) {
        int r = i >> 9, k = i & 511;
        int gr = (r >> 2) * Hh + u0 + (r & 3);
        float v = Whh[(size_t)gr * Hh + k];
        w4[r * HS2 + k] = pk(v, v);
    }
    // zero own slice of h state (layout [u][b])
    if (tid < 128) g_ht[0][(u0 + (tid >> 5)) * Bb + (tid & 31)] = 0.f;

    // pointwise ownership: tid<128 owns unit pu, batch pb; c in register
    const int pu = tid >> 5;
    const int pb = tid & 31;
    float c = 0.f;

    __syncthreads();
    unsigned bi = 1;
    if (tid == 0) {                              // barrier 0: zeros visible
        __threadfence();
        unsigned old = atomicAdd(&g_bar, 1u);
        if (old == NBLK * bi - 1u) g_rel = bi;
        while (g_rel < bi) {}
        __threadfence();
    }
    __syncthreads();
    bi++;

    for (int t = 0; t < Tt; t++) {
        // ---- prefetch xg for pointwise (tid<128: 4 gates) ----
        float xv0 = 0.f, xv1 = 0.f, xv2 = 0.f, xv3 = 0.f;
        if (tid < 128) {
            const float* xb = g_xgt + ((size_t)t * Gg + u0 + pu) * Bb + pb;
            xv0 = __ldg(xb);
            xv1 = __ldg(xb + (size_t)Hh * Bb);
            xv2 = __ldg(xb + (size_t)2 * Hh * Bb);
            xv3 = __ldg(xb + (size_t)3 * Hh * Bb);
        }

        // ---- stage h[u][b] (64KB) -> h2[p][k] pairs ----
        const float* hb = g_ht[t & 1];
        #pragma unroll
        for (int j = 0; j < 8; j++) {
            int idx = tid + j * NTH;             // float4 index, 4096 total
            int k = idx >> 3, pp = idx & 7;      // 8 float4 per unit row
            float4 v = __ldcg((const float4*)(hb + k * Bb + pp * 4));
            h2[(2 * pp)     * HS2 + k] = pk(v.x, v.y);
            h2[(2 * pp + 1) * HS2 + k] = pk(v.z, v.w);
        }
        __syncthreads();

        // ---- partials: 4 rows x 2 pairs (4 batches) x 32 k per lane ----
        ull a00 = 0, a01 = 0, a10 = 0, a11 = 0;
        ull a20 = 0, a21 = 0, a30 = 0, a31 = 0;
        const ull* hp0 = h2 + p8 * HS2 + k0;
        const ull* hp1 = h2 + (p8 + 8) * HS2 + k0;
        const ull* wq0 = w4 + (rg * 4 + 0) * HS2 + k0;
        const ull* wq1 = w4 + (rg * 4 + 1) * HS2 + k0;
        const ull* wq2 = w4 + (rg * 4 + 2) * HS2 + k0;
        const ull* wq3 = w4 + (rg * 4 + 3) * HS2 + k0;
        #pragma unroll 4
        for (int kk = 0; kk < 32; kk += 2) {
            ulonglong2 h0 = *(const ulonglong2*)(hp0 + kk);
            ulonglong2 h1 = *(const ulonglong2*)(hp1 + kk);
            ulonglong2 w0 = *(const ulonglong2*)(wq0 + kk);
            ulonglong2 w1 = *(const ulonglong2*)(wq1 + kk);
            ulonglong2 w2 = *(const ulonglong2*)(wq2 + kk);
            ulonglong2 w3 = *(const ulonglong2*)(wq3 + kk);
            fma2(a00, h0.x, w0.x); fma2(a01, h1.x, w0.x);
            fma2(a10, h0.x, w1.x); fma2(a11, h1.x, w1.x);
            fma2(a20, h0.x, w2.x); fma2(a21, h1.x, w2.x);
            fma2(a30, h0.x, w3.x); fma2(a31, h1.x, w3.x);
            fma2(a00, h0.y, w0.y); fma2(a01, h1.y, w0.y);
            fma2(a10, h0.y, w1.y); fma2(a11, h1.y, w1.y);
            fma2(a20, h0.y, w2.y); fma2(a21, h1.y, w2.y);
            fma2(a30, h0.y, w3.y); fma2(a31, h1.y, w3.y);
        }
        {
            // part[kc=w][r][p]: pp4[j*16] = row rg*4+j pair p8; +8 = pair p8+8
            ull* pp4 = part + ((size_t)w * 16 + rg * 4) * 16 + p8;
            pp4[0]  = a00; pp4[8]  = a01;
            pp4[16] = a10; pp4[24] = a11;
            pp4[32] = a20; pp4[40] = a21;
            pp4[48] = a30; pp4[56] = a31;
        }
        __syncthreads();

        // ---- reduce + activations + cell update (tid<128) ----
        if (tid < 128) {
            float pre[4] = {xv0, xv1, xv2, xv3};
            #pragma unroll
            for (int g = 0; g < 4; g++) {
                int r = g * 4 + pu;
                #pragma unroll
                for (int q = 0; q < 16; q++)
                    pre[g] += partf[(q * 16 + r) * 32 + pb];
            }
            float iv = sigf(pre[0]);
            float fv = sigf(pre[1]);
            float gv = tanh_f(pre[2]);
            float ov = sigf(pre[3]);
            c = fv * c + iv * gv;
            float h = ov * tanh_f(c);
            hseq[((size_t)pb * Tt + t) * Hh + u0 + pu] = h;      // [B][T][H]
            g_ht[(t + 1) & 1][(u0 + pu) * Bb + pb] = h;
        }
        __threadfence();
        __syncthreads();

        // ---- grid barrier (proven protocol) ----
        if (tid == 0) {
            unsigned old = atomicAdd(&g_bar, 1u);
            if (old == NBLK * bi - 1u) g_rel = bi;
            while (g_rel < bi) {}
            __threadfence();
        }
        __syncthreads();
        bi++;
    }
}

// ============================================================================
extern "C" void kernel_launch(void* const* d_in, const int* in_sizes, int n_in,
                              void* d_out, int out_size)
{
    const float* feats = (const float*)d_in[0];
    const float* Wih0  = (const float*)d_in[1];
    const float* Whh0  = (const float*)d_in[2];
    const float* bih0  = (const float*)d_in[3];
    const float* bhh0  = (const float*)d_in[4];
    const float* Wih1  = (const float*)d_in[5];
    const float* Whh1  = (const float*)d_in[6];
    const float* bih1  = (const float*)d_in[7];
    const float* bhh1  = (const float*)d_in[8];
    float* out = (float*)d_out;

    cudaFuncSetAttribute(lstm_rec, cudaFuncAttributeMaxDynamicSharedMemorySize, SMEM_REC);

    float* h1_ptr = nullptr;
    cudaGetSymbolAddress((void**)&h1_ptr, g_h1);

    dim3 ggrid(Mm / BM, Gg / BN);  // (128, 32)

    gemm_bias<<<ggrid, 256>>>(feats, Wih0, bih0, bhh0, 2048);
    reset_bar<<<1, 1>>>();
    lstm_rec<<<NBLK, NTH, SMEM_REC>>>(Whh0, h1_ptr);

    gemm_bias<<<ggrid, 256>>>(h1_ptr, Wih1, bih1, bhh1, 512);
    reset_bar<<<1, 1>>>();
    lstm_rec<<<NBLK, NTH, SMEM_REC>>>(Whh1, out);
}